// round 6
// baseline (speedup 1.0000x reference)
#include <cuda_runtime.h>
#include <cuda_bf16.h>
#include <cstddef>

// LIF recurrence: v = alpha*v + beta*c; s = (v >= 1); v = s ? 0 : v
// T sequential steps, N independent neurons. One thread per neuron (scalar),
// BLOCK=32 / grid=1024 so block count mod 148 SMs is nearly even (6.92/SM):
// fixes the 86.5% placement-balance ceiling of the 256-block float2 version,
// and doubles warps/SM to ~7 while keeping 28 KB/SM of loads in flight.
// Output layout: out[0 : T*N] = spikes, out[T*N : 2*T*N] = voltages.

#define T_STEPS 2048
#define N_NEUR  32768
#define UNROLL  32
#define BLOCK   32                     // 32768/32 = 1024 blocks, ~6.92 per SM

__device__ __forceinline__ void lif_step(float& v, float c, float& s_out, float& v_out) {
    const float alpha = (float)0.951229424500714;   // exp(-0.05), double -> f32
    const float beta  = (float)0.048770575499286;   // 1 - exp(-0.05), double -> f32
    v = alpha * v + beta * c;                       // FFMA
    const bool fire = (v >= 1.0f);
    s_out = fire ? 1.0f : 0.0f;
    v = fire ? 0.0f : v;                            // V_RESET = 0
    v_out = v;
}

__global__ void __launch_bounds__(BLOCK, 16)
lif_kernel(const float* __restrict__ cur,
           const float* __restrict__ v0,
           float* __restrict__ out)
{
    const int n = blockIdx.x * BLOCK + threadIdx.x;   // neuron id, 0..N-1

    float v = v0[n];

    const float* cp = cur + n;
    float* sp = out + n;                                      // spikes base
    float* vp = out + n + (size_t)T_STEPS * (size_t)N_NEUR;   // voltages base

    float bufA[UNROLL];
    float bufB[UNROLL];

    // Prologue: fill buffer A with steps [0, UNROLL)
    #pragma unroll
    for (int u = 0; u < UNROLL; ++u)
        bufA[u] = __ldcs(cp + (size_t)u * N_NEUR);

    // 2*UNROLL steps per iteration, double-buffered: while computing/storing
    // one chunk, the other chunk's UNROLL independent LDG.32s are in flight.
    for (int t = 0; t < T_STEPS; t += 2 * UNROLL) {
        // Issue loads for chunk B: steps [t+UNROLL, t+2*UNROLL)
        #pragma unroll
        for (int u = 0; u < UNROLL; ++u)
            bufB[u] = __ldcs(cp + (size_t)(t + UNROLL + u) * N_NEUR);

        // Compute + store chunk A
        #pragma unroll
        for (int u = 0; u < UNROLL; ++u) {
            float s, vo;
            lif_step(v, bufA[u], s, vo);
            const size_t off = (size_t)(t + u) * N_NEUR;
            __stcs(sp + off, s);
            __stcs(vp + off, vo);
        }

        // Issue loads for next chunk A: steps [t+2*UNROLL, t+3*UNROLL)
        if (t + 2 * UNROLL < T_STEPS) {
            #pragma unroll
            for (int u = 0; u < UNROLL; ++u)
                bufA[u] = __ldcs(cp + (size_t)(t + 2 * UNROLL + u) * N_NEUR);
        }

        // Compute + store chunk B
        #pragma unroll
        for (int u = 0; u < UNROLL; ++u) {
            float s, vo;
            lif_step(v, bufB[u], s, vo);
            const size_t off = (size_t)(t + UNROLL + u) * N_NEUR;
            __stcs(sp + off, s);
            __stcs(vp + off, vo);
        }
    }
}

extern "C" void kernel_launch(void* const* d_in, const int* in_sizes, int n_in,
                              void* d_out, int out_size)
{
    const float* currents = (const float*)d_in[0];   // (T, N) fp32
    const float* v0       = (const float*)d_in[1];   // (N,) fp32
    float* out            = (float*)d_out;           // 2*T*N fp32: [spikes; voltages]

    (void)in_sizes; (void)n_in; (void)out_size;

    lif_kernel<<<N_NEUR / BLOCK, BLOCK>>>(currents, v0, out);
}

// round 12
// speedup vs baseline: 1.0817x; 1.0817x over previous
#include <cuda_runtime.h>
#include <cuda_bf16.h>
#include <cstddef>
#include <cstdint>

// LIF recurrence: v = alpha*v + beta*c; s = (v >= 1); v = s ? 0 : v
// float2 per thread (2 neurons). Input staged through a PER-WARP private
// smem ring via cp.async.cg: each warp loads only its own 64 neurons'
// 256B/step rows; sync is the warp's own cp.async.wait_group + __syncwarp.
// R9 fix: pipeline TAIL — once no new chunks are issued, pending groups drop
// below AHEAD and wait_group<AHEAD-1> became a no-op (R7/R8 consumed the last
// 4 chunks before their copies landed -> ~5% voltage error). The last AHEAD
// iterations now drain with wait_group<0>.
// Output layout: out[0 : T*N] = spikes, out[T*N : 2*T*N] = voltages.

#define T_STEPS 2048
#define N_NEUR  32768
#define N2      (N_NEUR / 2)       // float2 elements per step = 16384
#define N4      (N_NEUR / 4)       // float4 elements per step = 8192
#define BLOCK   64                 // 2 warps; grid = 256
#define CHUNK   16                 // steps per cp.async group
#define NCHUNKS (T_STEPS / CHUNK)  // 128
#define SLOTS   6                  // ring depth in chunks (per warp)
#define AHEAD   5                  // chunk-groups in flight per warp

__device__ __forceinline__ void lif_step2(float2& v, float2 c, float2& s_out, float2& v_out) {
    const float alpha = (float)0.951229424500714;   // exp(-0.05), double -> f32
    const float beta  = (float)0.048770575499286;   // 1 - exp(-0.05), double -> f32
    v.x = alpha * v.x + beta * c.x;                 // FFMA
    v.y = alpha * v.y + beta * c.y;
    const bool fx = (v.x >= 1.0f);
    const bool fy = (v.y >= 1.0f);
    s_out.x = fx ? 1.0f : 0.0f;
    s_out.y = fy ? 1.0f : 0.0f;
    v.x = fx ? 0.0f : v.x;                          // V_RESET = 0
    v.y = fy ? 0.0f : v.y;
    v_out = v;
}

__device__ __forceinline__ void cp_async16(uint32_t smem_addr, const void* gmem_ptr) {
    asm volatile("cp.async.cg.shared.global [%0], [%1], 16;\n"
                 :: "r"(smem_addr), "l"(gmem_ptr) : "memory");
}
__device__ __forceinline__ void cp_commit() {
    asm volatile("cp.async.commit_group;\n" ::: "memory");
}
template <int N>
__device__ __forceinline__ void cp_wait() {
    asm volatile("cp.async.wait_group %0;\n" :: "n"(N) : "memory");
}

__global__ void __launch_bounds__(BLOCK, 4)
lif_kernel(const float4* __restrict__ cur4,   // currents viewed as float4
           const float2* __restrict__ v0,
           float2* __restrict__ out)
{
    // ring[warp][slot][step-in-chunk][lane] : 2*6*16*32*8 = 49152 B (48KB)
    __shared__ float2 ring[2][SLOTS][CHUNK][32];

    const int tid  = threadIdx.x;
    const int wid  = tid >> 5;
    const int lane = tid & 31;
    const int n    = blockIdx.x * BLOCK + tid;        // float2 lane, 0..N2-1

    float2 v = v0[n];

    float2* sp = out + n;                                  // spikes base
    float2* vp = out + n + (size_t)T_STEPS * (size_t)N2;   // voltages base

    // Producer mapping (per warp, 256B row per step = 16 float4):
    // lane = jj*16 + ii : ii = float4 index in row, jj = step parity.
    // Lane handles steps u = 2*u2 + jj, u2 = 0..7 -> 8 cp.async(16B)/chunk.
    const int ii = lane & 15;
    const int jj = lane >> 4;
    const float4* gsrc = cur4 + (size_t)blockIdx.x * 32 + (size_t)(wid * 16 + ii);

    const uint32_t ring_base = (uint32_t)__cvta_generic_to_shared(ring);

    auto issue_chunk = [&](int c) {
        const int slot = c % SLOTS;
        const uint32_t row0 = (uint32_t)(((wid * SLOTS + slot) * CHUNK) * 32 + ii * 2) * 8u;
        #pragma unroll
        for (int u2 = 0; u2 < CHUNK / 2; ++u2) {
            const int u = 2 * u2 + jj;
            const int t = c * CHUNK + u;
            const uint32_t dst = ring_base + row0 + (uint32_t)u * 256u;
            cp_async16(dst, gsrc + (size_t)t * N4);
        }
        cp_commit();
    };

    // Prologue: AHEAD chunks in flight (per warp).
    #pragma unroll
    for (int c = 0; c < AHEAD; ++c)
        issue_chunk(c);

    for (int c = 0; c < NCHUNKS; ++c) {
        // Steady state: 5 groups pending -> wait<4> drains chunk c.
        // Tail (no more issues): fewer than 5 pending -> wait<4> would be a
        // NO-OP; drain everything with wait<0> instead.
        if (c + AHEAD < NCHUNKS)
            cp_wait<AHEAD - 1>();
        else
            cp_wait<0>();
        __syncwarp();             // cross-lane visibility within the warp

        const int slot = c % SLOTS;

        // Consume chunk c: 16 steps (reads only this warp's ring region).
        #pragma unroll
        for (int u = 0; u < CHUNK; ++u) {
            const int t = c * CHUNK + u;
            float2 cc = ring[wid][slot][u][lane];
            float2 s, vo;
            lif_step2(v, cc, s, vo);
            const size_t off = (size_t)t * N2;
            __stcs(sp + off, s);
            __stcs(vp + off, vo);
        }

        // Refill: chunk c+AHEAD -> slot (c+5)%6 == (c-1)%6, which this warp
        // finished reading at iteration c-1 (warp program order -> safe WAR).
        if (c + AHEAD < NCHUNKS)
            issue_chunk(c + AHEAD);
    }
}

extern "C" void kernel_launch(void* const* d_in, const int* in_sizes, int n_in,
                              void* d_out, int out_size)
{
    const float4* currents = (const float4*)d_in[0];   // (T, N) fp32 as float4
    const float2* v0       = (const float2*)d_in[1];   // (N,) fp32 as float2
    float2* out            = (float2*)d_out;           // 2*T*N fp32: [spikes; voltages]

    (void)in_sizes; (void)n_in; (void)out_size;

    lif_kernel<<<N2 / BLOCK, BLOCK>>>(currents, v0, out);
}

// round 13
// speedup vs baseline: 1.1002x; 1.0171x over previous
#include <cuda_runtime.h>
#include <cuda_bf16.h>
#include <cstddef>
#include <cstdint>

// LIF recurrence: v = alpha*v + beta*c; s = (v >= 1); v = s ? 0 : v
// float2 per thread (2 neurons). Per-warp private smem ring via cp.async.cg.
// R12 -> R13: CHUNK 16->32, SLOTS 6->3, AHEAD 5->2. Latency coverage was
// shown to be ~10x oversupplied (not the binder); the remaining suspect is
// DRAM R/W bus-turnaround from fine-grained direction alternation. Doubling
// the chunk makes each warp issue 8KB unidirectional read bursts and 16KB
// write bursts, halving direction-flip frequency at the memory controller.
// Output layout: out[0 : T*N] = spikes, out[T*N : 2*T*N] = voltages.

#define T_STEPS 2048
#define N_NEUR  32768
#define N2      (N_NEUR / 2)       // float2 elements per step = 16384
#define N4      (N_NEUR / 4)       // float4 elements per step = 8192
#define BLOCK   64                 // 2 warps; grid = 256
#define CHUNK   32                 // steps per cp.async group (8KB/warp reads)
#define NCHUNKS (T_STEPS / CHUNK)  // 64
#define SLOTS   3                  // ring depth in chunks (per warp)
#define AHEAD   2                  // chunk-groups in flight per warp

__device__ __forceinline__ void lif_step2(float2& v, float2 c, float2& s_out, float2& v_out) {
    const float alpha = (float)0.951229424500714;   // exp(-0.05), double -> f32
    const float beta  = (float)0.048770575499286;   // 1 - exp(-0.05), double -> f32
    v.x = alpha * v.x + beta * c.x;                 // FFMA
    v.y = alpha * v.y + beta * c.y;
    const bool fx = (v.x >= 1.0f);
    const bool fy = (v.y >= 1.0f);
    s_out.x = fx ? 1.0f : 0.0f;
    s_out.y = fy ? 1.0f : 0.0f;
    v.x = fx ? 0.0f : v.x;                          // V_RESET = 0
    v.y = fy ? 0.0f : v.y;
    v_out = v;
}

__device__ __forceinline__ void cp_async16(uint32_t smem_addr, const void* gmem_ptr) {
    asm volatile("cp.async.cg.shared.global [%0], [%1], 16;\n"
                 :: "r"(smem_addr), "l"(gmem_ptr) : "memory");
}
__device__ __forceinline__ void cp_commit() {
    asm volatile("cp.async.commit_group;\n" ::: "memory");
}
template <int N>
__device__ __forceinline__ void cp_wait() {
    asm volatile("cp.async.wait_group %0;\n" :: "n"(N) : "memory");
}

__global__ void __launch_bounds__(BLOCK, 4)
lif_kernel(const float4* __restrict__ cur4,   // currents viewed as float4
           const float2* __restrict__ v0,
           float2* __restrict__ out)
{
    // ring[warp][slot][step-in-chunk][lane] : 2*3*32*32*8 = 49152 B (48KB)
    __shared__ float2 ring[2][SLOTS][CHUNK][32];

    const int tid  = threadIdx.x;
    const int wid  = tid >> 5;
    const int lane = tid & 31;
    const int n    = blockIdx.x * BLOCK + tid;        // float2 lane, 0..N2-1

    float2 v = v0[n];

    float2* sp = out + n;                                  // spikes base
    float2* vp = out + n + (size_t)T_STEPS * (size_t)N2;   // voltages base

    // Producer mapping (per warp, 256B row per step = 16 float4):
    // lane = jj*16 + ii : ii = float4 index in row, jj = step parity.
    // Lane handles steps u = 2*u2 + jj, u2 = 0..15 -> 16 cp.async(16B)/chunk.
    const int ii = lane & 15;
    const int jj = lane >> 4;
    const float4* gsrc = cur4 + (size_t)blockIdx.x * 32 + (size_t)(wid * 16 + ii);

    const uint32_t ring_base = (uint32_t)__cvta_generic_to_shared(ring);

    auto issue_chunk = [&](int c) {
        const int slot = c % SLOTS;
        const uint32_t row0 = (uint32_t)(((wid * SLOTS + slot) * CHUNK) * 32 + ii * 2) * 8u;
        #pragma unroll
        for (int u2 = 0; u2 < CHUNK / 2; ++u2) {
            const int u = 2 * u2 + jj;
            const int t = c * CHUNK + u;
            const uint32_t dst = ring_base + row0 + (uint32_t)u * 256u;
            cp_async16(dst, gsrc + (size_t)t * N4);
        }
        cp_commit();
    };

    // Prologue: AHEAD chunks in flight (per warp).
    #pragma unroll
    for (int c = 0; c < AHEAD; ++c)
        issue_chunk(c);

    for (int c = 0; c < NCHUNKS; ++c) {
        // Steady state: AHEAD groups pending -> wait<AHEAD-1> drains chunk c.
        // Tail (no more issues): fewer pending -> wait<AHEAD-1> would be a
        // NO-OP; drain everything with wait<0> instead.
        if (c + AHEAD < NCHUNKS)
            cp_wait<AHEAD - 1>();
        else
            cp_wait<0>();
        __syncwarp();             // cross-lane visibility within the warp

        const int slot = c % SLOTS;

        // Consume chunk c: 32 steps (reads only this warp's ring region).
        #pragma unroll
        for (int u = 0; u < CHUNK; ++u) {
            const int t = c * CHUNK + u;
            float2 cc = ring[wid][slot][u][lane];
            float2 s, vo;
            lif_step2(v, cc, s, vo);
            const size_t off = (size_t)t * N2;
            __stcs(sp + off, s);
            __stcs(vp + off, vo);
        }

        // Refill: chunk c+AHEAD -> slot (c+2)%3 == (c-1)%3, which this warp
        // finished reading at iteration c-1 (warp program order -> safe WAR).
        if (c + AHEAD < NCHUNKS)
            issue_chunk(c + AHEAD);
    }
}

extern "C" void kernel_launch(void* const* d_in, const int* in_sizes, int n_in,
                              void* d_out, int out_size)
{
    const float4* currents = (const float4*)d_in[0];   // (T, N) fp32 as float4
    const float2* v0       = (const float2*)d_in[1];   // (N,) fp32 as float2
    float2* out            = (float2*)d_out;           // 2*T*N fp32: [spikes; voltages]

    (void)in_sizes; (void)n_in; (void)out_size;

    lif_kernel<<<N2 / BLOCK, BLOCK>>>(currents, v0, out);
}